// round 4
// baseline (speedup 1.0000x reference)
#include <cuda_runtime.h>
#include <cuda_bf16.h>
#include <math.h>
#include <stdint.h>

#define BB 2
#define SS 2048
#define HH 2048
#define NH 16
#define HD 128
#define MM (BB*SS)   // 4096

// ---------------------------------------------------------------------------
// Scratch (device globals — allocation-free rule)
// ---------------------------------------------------------------------------
__device__ float g_Q[(size_t)MM*HH];
__device__ float g_K[(size_t)MM*HH];
__device__ float g_V[(size_t)MM*HH];
__device__ float g_A[(size_t)MM*HH];
__device__ __nv_bfloat16 g_Xh[(size_t)MM*HH];    // activation hi (X, later A)
__device__ __nv_bfloat16 g_Xl[(size_t)MM*HH];    // activation lo
__device__ __nv_bfloat16 g_Wh[4][(size_t)HH*HH]; // W^T hi (q,k,v,o)
__device__ __nv_bfloat16 g_Wl[4][(size_t)HH*HH]; // W^T lo

// ---------------------------------------------------------------------------
// PTX helpers (baseline sm_103 — NO tcgen05, NO 'a' features)
// ---------------------------------------------------------------------------
__device__ __forceinline__ uint32_t smem_to_u32(const void* p) {
    uint32_t a;
    asm("{ .reg .u64 t; cvta.to.shared.u64 t, %1; cvt.u32.u64 %0, t; }"
        : "=r"(a) : "l"(p));
    return a;
}
__device__ __forceinline__ void cp16(uint32_t dst, const void* src) {
    asm volatile("cp.async.cg.shared.global [%0], [%1], 16;" :: "r"(dst), "l"(src));
}
__device__ __forceinline__ void cp_commit() {
    asm volatile("cp.async.commit_group;" ::: "memory");
}
__device__ __forceinline__ void ldm4(uint32_t* r, uint32_t a) {
    asm volatile("ldmatrix.sync.aligned.m8n8.x4.shared.b16 {%0,%1,%2,%3}, [%4];"
        : "=r"(r[0]), "=r"(r[1]), "=r"(r[2]), "=r"(r[3]) : "r"(a));
}
__device__ __forceinline__ void mma16816(float* d, const uint32_t* a, const uint32_t* b) {
    asm volatile("mma.sync.aligned.m16n8k16.row.col.f32.bf16.bf16.f32 "
        "{%0,%1,%2,%3}, {%4,%5,%6,%7}, {%8,%9}, {%0,%1,%2,%3};"
        : "+f"(d[0]), "+f"(d[1]), "+f"(d[2]), "+f"(d[3])
        : "r"(a[0]), "r"(a[1]), "r"(a[2]), "r"(a[3]), "r"(b[0]), "r"(b[1]));
}

// ---------------------------------------------------------------------------
// Warp-MMA bf16 GEMM: C[M,2048] = (Ah+Al)[M,2048] @ (Bh+Bl)^T + bias
// B given as [N,K] (pre-transposed weights = col-major B for row.col mma).
// 128x128 CTA tile, 8 warps (2x4) of 64x32, K chunks of 32, 4-stage cp.async.
// 3-pass hi/lo compensation, fp32 accumulate.
// ---------------------------------------------------------------------------
#define GT_THREADS 256
#define KC 32
#define NCH (HH/KC)          // 64
#define STG 4
#define ROWB 80              // 32 halves (64B) + 16B pad per smem row
#define MATB (128*ROWB)      // 10240 B per matrix tile
#define STGB (4*MATB)        // Ah,Al,Bh,Bl per stage = 40960 B
#define GSMEM (STG*STGB)     // 163840 B

__global__ __launch_bounds__(GT_THREADS, 1)
void gemm_tc(const __nv_bfloat16* __restrict__ Ah,
             const __nv_bfloat16* __restrict__ Al,
             const __nv_bfloat16* __restrict__ Bh,
             const __nv_bfloat16* __restrict__ Bl,
             const float* __restrict__ bias,
             float* __restrict__ C)
{
    extern __shared__ char sm_[];
    const uint32_t sb = smem_to_u32(sm_);
    const int tid  = threadIdx.x;
    const int wid  = tid >> 5;
    const int lane = tid & 31;
    const int bm = blockIdx.y * 128;
    const int bn = blockIdx.x * 128;
    const int wm = (wid >> 2) * 64;     // warp m offset in tile
    const int wn = (wid & 3) * 32;      // warp n offset in tile
    const int grp = lane >> 2;          // 0..7
    const int tig = lane & 3;           // 0..3

    float acc[4][4][4];
#pragma unroll
    for (int m = 0; m < 4; m++)
#pragma unroll
        for (int n = 0; n < 4; n++)
#pragma unroll
            for (int e = 0; e < 4; e++) acc[m][n][e] = 0.f;

    // ---- chunk loader: 4 matrices x 128 rows x 64B, 16B per cp.async
    auto load_chunk = [&](int ch, int s) {
        const uint32_t st = sb + s * STGB;
        const size_t kofs = (size_t)ch * KC;
        const int c  = tid & 3;          // 16B sub-chunk
        const int r0 = tid >> 2;         // 0..63
#pragma unroll
        for (int it = 0; it < 8; it++) {
            const int mat = it >> 1;                 // 0:Ah 1:Al 2:Bh 3:Bl
            const int row = ((it & 1) << 6) + r0;    // 0..127
            const __nv_bfloat16* g =
                (mat == 0) ? Ah + (size_t)(bm + row) * HH :
                (mat == 1) ? Al + (size_t)(bm + row) * HH :
                (mat == 2) ? Bh + (size_t)(bn + row) * HH :
                             Bl + (size_t)(bn + row) * HH;
            cp16(st + mat * MATB + row * ROWB + c * 16, g + kofs + c * 8);
        }
        cp_commit();
    };

    // prologue: stages 0..STG-2
#pragma unroll
    for (int c = 0; c < STG - 1; c++) load_chunk(c, c);

    // ldmatrix lane addressing (constant per thread)
    const int a_row = lane & 15;              // m row within 16
    const int a_kb  = (lane >> 4) * 16;       // k byte offset (0 or 16)
    const int b_row = (lane & 7) + ((lane & 16) >> 1);   // n row within 16
    const int b_kb  = (lane & 8) << 1;        // k byte offset (0 or 16)

    for (int c = 0; c < NCH; c++) {
        asm volatile("cp.async.wait_group %0;" :: "n"(STG - 2) : "memory");
        __syncthreads();

        const int nc = c + STG - 1;
        if (nc < NCH) load_chunk(nc, nc % STG);

        const uint32_t st  = sb + (c % STG) * STGB;
        const uint32_t aAh = st + wm * ROWB;
        const uint32_t aAl = st + MATB + wm * ROWB;
        const uint32_t aBh = st + 2 * MATB + wn * ROWB;
        const uint32_t aBl = st + 3 * MATB + wn * ROWB;

#pragma unroll
        for (int k16 = 0; k16 < 2; k16++) {
            const int kb = 32 * k16;
            uint32_t ah[4][4], al[4][4];
#pragma unroll
            for (int m = 0; m < 4; m++) {
                const uint32_t ro = (m * 16 + a_row) * ROWB + kb + a_kb;
                ldm4(ah[m], aAh + ro);
                ldm4(al[m], aAl + ro);
            }
            uint32_t bh[2][4], bl[2][4];
#pragma unroll
            for (int g = 0; g < 2; g++) {
                const uint32_t ro = (g * 16 + b_row) * ROWB + kb + b_kb;
                ldm4(bh[g], aBh + ro);
                ldm4(bl[g], aBl + ro);
            }
#pragma unroll
            for (int m = 0; m < 4; m++)
#pragma unroll
                for (int g = 0; g < 2; g++)
#pragma unroll
                    for (int j = 0; j < 2; j++) {
                        const int n = 2 * g + j;
                        mma16816(acc[m][n], ah[m], &bh[g][2 * j]);
                        mma16816(acc[m][n], ah[m], &bl[g][2 * j]);
                        mma16816(acc[m][n], al[m], &bh[g][2 * j]);
                    }
        }
    }

    // epilogue: acc -> C (+bias)
#pragma unroll
    for (int m = 0; m < 4; m++) {
        const int row0 = bm + wm + m * 16 + grp;
#pragma unroll
        for (int n = 0; n < 4; n++) {
            const int col = bn + wn + n * 8 + tig * 2;
            const float2 bv = *(const float2*)(bias + col);
            float2 o0, o1;
            o0.x = acc[m][n][0] + bv.x;  o0.y = acc[m][n][1] + bv.y;
            o1.x = acc[m][n][2] + bv.x;  o1.y = acc[m][n][3] + bv.y;
            *(float2*)(C + (size_t)row0 * HH + col)       = o0;
            *(float2*)(C + (size_t)(row0 + 8) * HH + col) = o1;
        }
    }
}

// ---------------------------------------------------------------------------
// fp32 -> bf16 hi/lo split (elementwise), used for X and attention output A
// ---------------------------------------------------------------------------
__global__ void fsplit_kernel(const float* __restrict__ X,
                              __nv_bfloat16* __restrict__ H,
                              __nv_bfloat16* __restrict__ L, int n)
{
    int i = (blockIdx.x * blockDim.x + threadIdx.x) * 4;
    if (i >= n) return;
    float4 v = *(const float4*)(X + i);
    __nv_bfloat16 h0 = __float2bfloat16(v.x);
    __nv_bfloat16 h1 = __float2bfloat16(v.y);
    __nv_bfloat16 h2 = __float2bfloat16(v.z);
    __nv_bfloat16 h3 = __float2bfloat16(v.w);
    __nv_bfloat162 hh0(h0, h1), hh1(h2, h3);
    __nv_bfloat162 ll0(__float2bfloat16(v.x - __bfloat162float(h0)),
                       __float2bfloat16(v.y - __bfloat162float(h1)));
    __nv_bfloat162 ll1(__float2bfloat16(v.z - __bfloat162float(h2)),
                       __float2bfloat16(v.w - __bfloat162float(h3)));
    *(__nv_bfloat162*)(H + i)     = hh0;
    *(__nv_bfloat162*)(H + i + 2) = hh1;
    *(__nv_bfloat162*)(L + i)     = ll0;
    *(__nv_bfloat162*)(L + i + 2) = ll1;
}

// ---------------------------------------------------------------------------
// Weight transpose + split: W[K,N] fp32 -> Th,Tl[N,K] bf16
// ---------------------------------------------------------------------------
__global__ void wsplit_t_kernel(const float* __restrict__ W,
                                __nv_bfloat16* __restrict__ Th,
                                __nv_bfloat16* __restrict__ Tl)
{
    __shared__ float t[32][33];
    const int bx = blockIdx.x * 32;   // n
    const int by = blockIdx.y * 32;   // k
    const int x = threadIdx.x, y = threadIdx.y;
#pragma unroll
    for (int i = 0; i < 32; i += 8)
        t[y+i][x] = W[(size_t)(by + y + i) * HH + bx + x];
    __syncthreads();
#pragma unroll
    for (int i = 0; i < 32; i += 8) {
        float v = t[x][y+i];
        __nv_bfloat16 h = __float2bfloat16(v);
        __nv_bfloat16 l = __float2bfloat16(v - __bfloat162float(h));
        size_t o = (size_t)(bx + y + i) * HH + by + x;
        Th[o] = h;
        Tl[o] = l;
    }
}

// ---------------------------------------------------------------------------
// Flash attention (fp32 SIMT) — unchanged (passing)
// ---------------------------------------------------------------------------
#define LDQ 132
#define LDP 65
#define ATTN_SMEM_BYTES ((2*64*LDQ + 64*LDP) * (int)sizeof(float))

__global__ __launch_bounds__(256, 2)
void attn_kernel()
{
    extern __shared__ float sm[];
    float* sq  = sm;
    float* skv = sm + 64 * LDQ;
    float* sp  = sm + 2 * 64 * LDQ;

    const int tid = threadIdx.x;
    const int tx  = tid & 15;
    const int ty  = tid >> 4;
    const int qt  = blockIdx.x;
    const int h   = blockIdx.y;
    const int b   = blockIdx.z;

    const float scale = rsqrtf((float)HD);

    const float* Qg = g_Q + ((size_t)b * SS + (size_t)qt * 64) * HH + h * HD;
    const float* Kg = g_K + (size_t)b * SS * HH + h * HD;
    const float* Vg = g_V + (size_t)b * SS * HH + h * HD;
    float*       Og = g_A + ((size_t)b * SS + (size_t)qt * 64) * HH + h * HD;

    for (int u = tid; u < 64 * 32; u += 256) {
        int r = u >> 5, c4 = (u & 31) * 4;
        float4 v = *(const float4*)(Qg + (size_t)r * HH + c4);
        v.x *= scale; v.y *= scale; v.z *= scale; v.w *= scale;
        *(float4*)(sq + r * LDQ + c4) = v;
    }

    float4 acc0[4], acc1[4];
#pragma unroll
    for (int i = 0; i < 4; i++) {
        acc0[i] = make_float4(0.f, 0.f, 0.f, 0.f);
        acc1[i] = make_float4(0.f, 0.f, 0.f, 0.f);
    }
    float mrow[4] = {-INFINITY, -INFINITY, -INFINITY, -INFINITY};
    float lrow[4] = {0.f, 0.f, 0.f, 0.f};

    for (int kt = 0; kt < SS; kt += 64) {
        for (int u = tid; u < 64 * 32; u += 256) {
            int r = u >> 5, c4 = (u & 31) * 4;
            *(float4*)(skv + r * LDQ + c4) =
                *(const float4*)(Kg + (size_t)(kt + r) * HH + c4);
        }
        __syncthreads();

        float s[4][4];
#pragma unroll
        for (int i = 0; i < 4; i++)
#pragma unroll
            for (int j = 0; j < 4; j++) s[i][j] = 0.f;

#pragma unroll 8
        for (int d4 = 0; d4 < 32; d4++) {
            float4 qv[4], kv[4];
#pragma unroll
            for (int i = 0; i < 4; i++)
                qv[i] = *(const float4*)(sq + (4 * ty + i) * LDQ + d4 * 4);
#pragma unroll
            for (int j = 0; j < 4; j++)
                kv[j] = *(const float4*)(skv + (4 * tx + j) * LDQ + d4 * 4);
#pragma unroll
            for (int i = 0; i < 4; i++)
#pragma unroll
                for (int j = 0; j < 4; j++) {
                    s[i][j] = fmaf(qv[i].x, kv[j].x, s[i][j]);
                    s[i][j] = fmaf(qv[i].y, kv[j].y, s[i][j]);
                    s[i][j] = fmaf(qv[i].z, kv[j].z, s[i][j]);
                    s[i][j] = fmaf(qv[i].w, kv[j].w, s[i][j]);
                }
        }

        float alpha[4];
#pragma unroll
        for (int i = 0; i < 4; i++) {
            float mx = fmaxf(fmaxf(s[i][0], s[i][1]), fmaxf(s[i][2], s[i][3]));
#pragma unroll
            for (int off = 8; off > 0; off >>= 1)
                mx = fmaxf(mx, __shfl_xor_sync(0xffffffffu, mx, off, 16));
            float mn = fmaxf(mrow[i], mx);
            float rs = 0.f;
#pragma unroll
            for (int j = 0; j < 4; j++) {
                float p = __expf(s[i][j] - mn);
                sp[(4 * ty + i) * LDP + 4 * tx + j] = p;
                rs += p;
            }
#pragma unroll
            for (int off = 8; off > 0; off >>= 1)
                rs += __shfl_xor_sync(0xffffffffu, rs, off, 16);
            alpha[i] = __expf(mrow[i] - mn);
            lrow[i]  = alpha[i] * lrow[i] + rs;
            mrow[i]  = mn;
        }
        __syncthreads();

        for (int u = tid; u < 64 * 32; u += 256) {
            int r = u >> 5, c4 = (u & 31) * 4;
            *(float4*)(skv + r * LDQ + c4) =
                *(const float4*)(Vg + (size_t)(kt + r) * HH + c4);
        }
        __syncthreads();

#pragma unroll
        for (int i = 0; i < 4; i++) {
            float a = alpha[i];
            acc0[i].x *= a; acc0[i].y *= a; acc0[i].z *= a; acc0[i].w *= a;
            acc1[i].x *= a; acc1[i].y *= a; acc1[i].z *= a; acc1[i].w *= a;
        }
#pragma unroll 4
        for (int j = 0; j < 64; j++) {
            float4 v0 = *(const float4*)(skv + j * LDQ + tx * 4);
            float4 v1 = *(const float4*)(skv + j * LDQ + 64 + tx * 4);
#pragma unroll
            for (int i = 0; i < 4; i++) {
                float p = sp[(4 * ty + i) * LDP + j];
                acc0[i].x = fmaf(p, v0.x, acc0[i].x);
                acc0[i].y = fmaf(p, v0.y, acc0[i].y);
                acc0[i].z = fmaf(p, v0.z, acc0[i].z);
                acc0[i].w = fmaf(p, v0.w, acc0[i].w);
                acc1[i].x = fmaf(p, v1.x, acc1[i].x);
                acc1[i].y = fmaf(p, v1.y, acc1[i].y);
                acc1[i].z = fmaf(p, v1.z, acc1[i].z);
                acc1[i].w = fmaf(p, v1.w, acc1[i].w);
            }
        }
        __syncthreads();
    }

#pragma unroll
    for (int i = 0; i < 4; i++) {
        float inv = 1.f / lrow[i];
        float4 o0 = acc0[i], o1 = acc1[i];
        o0.x *= inv; o0.y *= inv; o0.z *= inv; o0.w *= inv;
        o1.x *= inv; o1.y *= inv; o1.z *= inv; o1.w *= inv;
        *(float4*)(Og + (size_t)(4 * ty + i) * HH + tx * 4)      = o0;
        *(float4*)(Og + (size_t)(4 * ty + i) * HH + 64 + tx * 4) = o1;
    }
}

// ---------------------------------------------------------------------------
extern "C" void kernel_launch(void* const* d_in, const int* in_sizes, int n_in,
                              void* d_out, int out_size)
{
    const float* X  = (const float*)d_in[0];
    const float* Wq = (const float*)d_in[1];
    const float* bq = (const float*)d_in[2];
    const float* Wk = (const float*)d_in[3];
    const float* bk = (const float*)d_in[4];
    const float* Wv = (const float*)d_in[5];
    const float* bv = (const float*)d_in[6];
    const float* Wo = (const float*)d_in[7];
    const float* bo = (const float*)d_in[8];
    float* out = (float*)d_out;

    float* dQ; cudaGetSymbolAddress((void**)&dQ, g_Q);
    float* dK; cudaGetSymbolAddress((void**)&dK, g_K);
    float* dV; cudaGetSymbolAddress((void**)&dV, g_V);
    float* dA; cudaGetSymbolAddress((void**)&dA, g_A);
    __nv_bfloat16* dXh; cudaGetSymbolAddress((void**)&dXh, g_Xh);
    __nv_bfloat16* dXl; cudaGetSymbolAddress((void**)&dXl, g_Xl);
    __nv_bfloat16* dWh; cudaGetSymbolAddress((void**)&dWh, g_Wh);
    __nv_bfloat16* dWl; cudaGetSymbolAddress((void**)&dWl, g_Wl);
    const size_t WSZ = (size_t)HH * HH;

    cudaFuncSetAttribute(gemm_tc, cudaFuncAttributeMaxDynamicSharedMemorySize, GSMEM);
    cudaFuncSetAttribute(attn_kernel, cudaFuncAttributeMaxDynamicSharedMemorySize,
                         ATTN_SMEM_BYTES);

    const int nX = MM * HH;
    fsplit_kernel<<<nX/1024, 256>>>(X, dXh, dXl, nX);
    dim3 tb(32, 8), tg(HH/32, HH/32);
    wsplit_t_kernel<<<tg, tb>>>(Wq, dWh + 0*WSZ, dWl + 0*WSZ);
    wsplit_t_kernel<<<tg, tb>>>(Wk, dWh + 1*WSZ, dWl + 1*WSZ);
    wsplit_t_kernel<<<tg, tb>>>(Wv, dWh + 2*WSZ, dWl + 2*WSZ);
    wsplit_t_kernel<<<tg, tb>>>(Wo, dWh + 3*WSZ, dWl + 3*WSZ);

    dim3 gg(HH/128, MM/128);
    gemm_tc<<<gg, GT_THREADS, GSMEM>>>(dXh, dXl, dWh + 0*WSZ, dWl + 0*WSZ, bq, dQ);
    gemm_tc<<<gg, GT_THREADS, GSMEM>>>(dXh, dXl, dWh + 1*WSZ, dWl + 1*WSZ, bk, dK);
    gemm_tc<<<gg, GT_THREADS, GSMEM>>>(dXh, dXl, dWh + 2*WSZ, dWl + 2*WSZ, bv, dV);

    dim3 agrid(SS/64, NH, BB);
    attn_kernel<<<agrid, 256, ATTN_SMEM_BYTES>>>();

    fsplit_kernel<<<nX/1024, 256>>>(dA, dXh, dXl, nX);
    gemm_tc<<<gg, GT_THREADS, GSMEM>>>(dXh, dXl, dWh + 3*WSZ, dWl + 3*WSZ, bo, out);
}

// round 5
// speedup vs baseline: 1.1781x; 1.1781x over previous
#include <cuda_runtime.h>
#include <math.h>
#include <stdint.h>

#define BB 2
#define SS 2048
#define HH 2048
#define NH 16
#define HD 128
#define MM (BB*SS)   // 4096

typedef unsigned long long ull;

// Scratch (device globals — allocation-free rule)
__device__ float g_Q[(size_t)MM*HH];
__device__ float g_K[(size_t)MM*HH];
__device__ float g_V[(size_t)MM*HH];
__device__ float g_A[(size_t)MM*HH];

// ---------------------------------------------------------------------------
// Packed f32x2 helpers (Blackwell FFMA2 — PTX-only pattern)
// ---------------------------------------------------------------------------
__device__ __forceinline__ void fma2(ull& d, ull a, ull b) {
    asm("fma.rn.f32x2 %0, %1, %2, %0;" : "+l"(d) : "l"(a), "l"(b));
}
__device__ __forceinline__ void mul2(ull& d, ull a) {
    asm("mul.rn.f32x2 %0, %0, %1;" : "+l"(d) : "l"(a));
}
__device__ __forceinline__ ull pk2(float x, float y) {
    ull r;
    asm("mov.b64 %0, {%1, %2};" : "=l"(r)
        : "r"(__float_as_uint(x)), "r"(__float_as_uint(y)));
    return r;
}
__device__ __forceinline__ float2 upk2(ull v) {
    uint32_t lo, hi;
    asm("mov.b64 {%0, %1}, %2;" : "=r"(lo), "=r"(hi) : "l"(v));
    return make_float2(__uint_as_float(lo), __uint_as_float(hi));
}

// ---------------------------------------------------------------------------
// SGEMM (f32x2): C[M,N] = A[M,K] @ W[K,N] + bias[N]
// 128x128 tile, BK=8, 256 threads, 8x8 per-thread tile as 8x4 packed pairs.
// ---------------------------------------------------------------------------
__global__ __launch_bounds__(256, 2)
void gemm_f32x2(const float* __restrict__ A, const float* __restrict__ W,
                const float* __restrict__ bias, float* __restrict__ C,
                int M, int N, int K)
{
    __shared__ __align__(16) float As[8][128];   // As[k][m]
    __shared__ __align__(16) float Bs[8][128];   // Bs[k][n]

    const int tid = threadIdx.x;
    const int tr  = tid >> 4;      // 0..15
    const int tc  = tid & 15;      // 0..15
    const int bm  = blockIdx.y * 128;
    const int bn  = blockIdx.x * 128;

    ull acc[8][4];
#pragma unroll
    for (int i = 0; i < 8; i++)
#pragma unroll
        for (int p = 0; p < 4; p++) acc[i][p] = 0ull;

    const float* Ab = A + (size_t)bm * K;
    const float* Wb = W + bn;

    const int a_row = tid >> 1;          // 0..127
    const int a_k4  = (tid & 1) * 4;     // 0 or 4
    const int b_row = tid >> 5;          // 0..7
    const int b_c4  = (tid & 31) * 4;    // 0..124

    for (int kt = 0; kt < K; kt += 8) {
        float4 av = *(const float4*)(Ab + (size_t)a_row * K + kt + a_k4);
        As[a_k4 + 0][a_row] = av.x;
        As[a_k4 + 1][a_row] = av.y;
        As[a_k4 + 2][a_row] = av.z;
        As[a_k4 + 3][a_row] = av.w;
        *(float4*)&Bs[b_row][b_c4] =
            *(const float4*)(Wb + (size_t)(kt + b_row) * N + b_c4);
        __syncthreads();

#pragma unroll
        for (int k = 0; k < 8; k++) {
            float4 a0 = *(const float4*)&As[k][tr * 4];
            float4 a1 = *(const float4*)&As[k][64 + tr * 4];
            ulonglong2 bp0 = *(const ulonglong2*)&Bs[k][tc * 4];
            ulonglong2 bp1 = *(const ulonglong2*)&Bs[k][64 + tc * 4];
            ull am[8];
            am[0] = pk2(a0.x, a0.x); am[1] = pk2(a0.y, a0.y);
            am[2] = pk2(a0.z, a0.z); am[3] = pk2(a0.w, a0.w);
            am[4] = pk2(a1.x, a1.x); am[5] = pk2(a1.y, a1.y);
            am[6] = pk2(a1.z, a1.z); am[7] = pk2(a1.w, a1.w);
#pragma unroll
            for (int i = 0; i < 8; i++) {
                fma2(acc[i][0], am[i], bp0.x);
                fma2(acc[i][1], am[i], bp0.y);
                fma2(acc[i][2], am[i], bp1.x);
                fma2(acc[i][3], am[i], bp1.y);
            }
        }
        __syncthreads();
    }

    // epilogue: rows {bm+tr*4+i, bm+64+tr*4+i}, cols {bn+tc*4, bn+64+tc*4}
#pragma unroll
    for (int i = 0; i < 8; i++) {
        const int row = bm + ((i >> 2) ? 64 : 0) + tr * 4 + (i & 3);
#pragma unroll
        for (int jg = 0; jg < 2; jg++) {
            const int col = bn + jg * 64 + tc * 4;
            float4 bb = *(const float4*)(bias + col);
            float2 p0 = upk2(acc[i][jg * 2 + 0]);
            float2 p1 = upk2(acc[i][jg * 2 + 1]);
            float4 o;
            o.x = p0.x + bb.x; o.y = p0.y + bb.y;
            o.z = p1.x + bb.z; o.w = p1.y + bb.w;
            *(float4*)(C + (size_t)row * N + col) = o;
        }
    }
}

// ---------------------------------------------------------------------------
// Flash attention (fp32, f32x2 math): 64 query rows per CTA, 64-row K/V tiles.
// ---------------------------------------------------------------------------
#define LDQ 132
#define LDP 65
#define ATTN_SMEM_BYTES ((2*64*LDQ + 64*LDP) * (int)sizeof(float))

__global__ __launch_bounds__(256, 2)
void attn_kernel()
{
    extern __shared__ float sm[];
    float* sq  = sm;                 // 64 x LDQ
    float* skv = sm + 64 * LDQ;      // 64 x LDQ (K then V)
    float* sp  = sm + 2 * 64 * LDQ;  // 64 x LDP

    const int tid = threadIdx.x;
    const int tx  = tid & 15;
    const int ty  = tid >> 4;
    const int qt  = blockIdx.x;
    const int h   = blockIdx.y;
    const int b   = blockIdx.z;

    const float scale = rsqrtf((float)HD);

    const float* Qg = g_Q + ((size_t)b * SS + (size_t)qt * 64) * HH + h * HD;
    const float* Kg = g_K + (size_t)b * SS * HH + h * HD;
    const float* Vg = g_V + (size_t)b * SS * HH + h * HD;
    float*       Og = g_A + ((size_t)b * SS + (size_t)qt * 64) * HH + h * HD;

    for (int u = tid; u < 64 * 32; u += 256) {
        int r = u >> 5, c4 = (u & 31) * 4;
        float4 v = *(const float4*)(Qg + (size_t)r * HH + c4);
        v.x *= scale; v.y *= scale; v.z *= scale; v.w *= scale;
        *(float4*)(sq + r * LDQ + c4) = v;
    }

    ull a0[4][2], a1[4][2];     // output accum: 4 rows x 16 d-cols (as pairs)
#pragma unroll
    for (int i = 0; i < 4; i++) {
        a0[i][0] = a0[i][1] = 0ull;
        a1[i][0] = a1[i][1] = 0ull;
    }
    float mrow[4] = {-INFINITY, -INFINITY, -INFINITY, -INFINITY};
    float lrow[4] = {0.f, 0.f, 0.f, 0.f};

    for (int kt = 0; kt < SS; kt += 64) {
        for (int u = tid; u < 64 * 32; u += 256) {
            int r = u >> 5, c4 = (u & 31) * 4;
            *(float4*)(skv + r * LDQ + c4) =
                *(const float4*)(Kg + (size_t)(kt + r) * HH + c4);
        }
        __syncthreads();

        // scores (packed over d): s2[i][j] accumulates (even,odd) halves
        ull s2[4][4];
#pragma unroll
        for (int i = 0; i < 4; i++)
#pragma unroll
            for (int j = 0; j < 4; j++) s2[i][j] = 0ull;

#pragma unroll 8
        for (int d4 = 0; d4 < 32; d4++) {
            ulonglong2 qp[4];
#pragma unroll
            for (int i = 0; i < 4; i++)
                qp[i] = *(const ulonglong2*)(sq + (4 * ty + i) * LDQ + d4 * 4);
#pragma unroll
            for (int j = 0; j < 4; j++) {
                ulonglong2 kp =
                    *(const ulonglong2*)(skv + (4 * tx + j) * LDQ + d4 * 4);
#pragma unroll
                for (int i = 0; i < 4; i++) {
                    fma2(s2[i][j], qp[i].x, kp.x);
                    fma2(s2[i][j], qp[i].y, kp.y);
                }
            }
        }

        float alpha[4];
#pragma unroll
        for (int i = 0; i < 4; i++) {
            float s[4];
#pragma unroll
            for (int j = 0; j < 4; j++) {
                float2 f = upk2(s2[i][j]);
                s[j] = f.x + f.y;
            }
            float mx = fmaxf(fmaxf(s[0], s[1]), fmaxf(s[2], s[3]));
#pragma unroll
            for (int off = 8; off > 0; off >>= 1)
                mx = fmaxf(mx, __shfl_xor_sync(0xffffffffu, mx, off, 16));
            float mn = fmaxf(mrow[i], mx);
            float rs = 0.f;
#pragma unroll
            for (int j = 0; j < 4; j++) {
                float p = __expf(s[j] - mn);
                sp[(4 * ty + i) * LDP + 4 * tx + j] = p;
                rs += p;
            }
#pragma unroll
            for (int off = 8; off > 0; off >>= 1)
                rs += __shfl_xor_sync(0xffffffffu, rs, off, 16);
            alpha[i] = __expf(mrow[i] - mn);
            lrow[i]  = alpha[i] * lrow[i] + rs;
            mrow[i]  = mn;
        }
        __syncthreads();   // P written, done reading K

        for (int u = tid; u < 64 * 32; u += 256) {
            int r = u >> 5, c4 = (u & 31) * 4;
            *(float4*)(skv + r * LDQ + c4) =
                *(const float4*)(Vg + (size_t)(kt + r) * HH + c4);
        }
        __syncthreads();

        // rescale accumulators (packed)
#pragma unroll
        for (int i = 0; i < 4; i++) {
            ull ap = pk2(alpha[i], alpha[i]);
            mul2(a0[i][0], ap); mul2(a0[i][1], ap);
            mul2(a1[i][0], ap); mul2(a1[i][1], ap);
        }

        // P @ V (V consumed as packed pairs, P duplicated)
#pragma unroll 4
        for (int j = 0; j < 64; j++) {
            ulonglong2 v0 = *(const ulonglong2*)(skv + j * LDQ + tx * 4);
            ulonglong2 v1 = *(const ulonglong2*)(skv + j * LDQ + 64 + tx * 4);
#pragma unroll
            for (int i = 0; i < 4; i++) {
                float p = sp[(4 * ty + i) * LDP + j];
                ull pp = pk2(p, p);
                fma2(a0[i][0], pp, v0.x);
                fma2(a0[i][1], pp, v0.y);
                fma2(a1[i][0], pp, v1.x);
                fma2(a1[i][1], pp, v1.y);
            }
        }
        __syncthreads();
    }

    // epilogue: O = acc / l  (packed scale, direct 16B stores)
#pragma unroll
    for (int i = 0; i < 4; i++) {
        float inv = 1.f / lrow[i];
        ull ip = pk2(inv, inv);
        mul2(a0[i][0], ip); mul2(a0[i][1], ip);
        mul2(a1[i][0], ip); mul2(a1[i][1], ip);
        ulonglong2 o0; o0.x = a0[i][0]; o0.y = a0[i][1];
        ulonglong2 o1; o1.x = a1[i][0]; o1.y = a1[i][1];
        *(ulonglong2*)(Og + (size_t)(4 * ty + i) * HH + tx * 4)      = o0;
        *(ulonglong2*)(Og + (size_t)(4 * ty + i) * HH + 64 + tx * 4) = o1;
    }
}

// ---------------------------------------------------------------------------
extern "C" void kernel_launch(void* const* d_in, const int* in_sizes, int n_in,
                              void* d_out, int out_size)
{
    const float* X  = (const float*)d_in[0];
    const float* Wq = (const float*)d_in[1];
    const float* bq = (const float*)d_in[2];
    const float* Wk = (const float*)d_in[3];
    const float* bk = (const float*)d_in[4];
    const float* Wv = (const float*)d_in[5];
    const float* bv = (const float*)d_in[6];
    const float* Wo = (const float*)d_in[7];
    const float* bo = (const float*)d_in[8];
    float* out = (float*)d_out;

    float* dQ; cudaGetSymbolAddress((void**)&dQ, g_Q);
    float* dK; cudaGetSymbolAddress((void**)&dK, g_K);
    float* dV; cudaGetSymbolAddress((void**)&dV, g_V);
    float* dA; cudaGetSymbolAddress((void**)&dA, g_A);

    cudaFuncSetAttribute(attn_kernel,
                         cudaFuncAttributeMaxDynamicSharedMemorySize,
                         ATTN_SMEM_BYTES);

    dim3 ggrid(HH / 128, MM / 128);
    gemm_f32x2<<<ggrid, 256>>>(X, Wq, bq, dQ, MM, HH, HH);
    gemm_f32x2<<<ggrid, 256>>>(X, Wk, bk, dK, MM, HH, HH);
    gemm_f32x2<<<ggrid, 256>>>(X, Wv, bv, dV, MM, HH, HH);

    dim3 agrid(SS / 64, NH, BB);
    attn_kernel<<<agrid, 256, ATTN_SMEM_BYTES>>>();

    gemm_f32x2<<<ggrid, 256>>>(dA, Wo, bo, out, MM, HH, HH);
}